// round 8
// baseline (speedup 1.0000x reference)
#include <cuda_runtime.h>
#include <cstdint>

#define BATCH 131072
#define NF    64
#define RPW   8            // rows per warp-group-iteration (4 pairs)
#define NGROUPS (BATCH / RPW)   // 16384 row-groups
#define GRID  888          // 148 SMs x 6 blocks -> exactly one wave
#define WARPS_TOTAL (GRID * 8)  // 7104 warps

__global__ __launch_bounds__(256, 6) void svd_predict_kernel(
    const int*   __restrict__ user_item,   // [BATCH, 2]
    const float* __restrict__ pu,          // [N_USERS, 64]
    const float* __restrict__ qi,          // [N_ITEMS, 64]
    const float* __restrict__ bu,          // [N_USERS]
    const float* __restrict__ bi,          // [N_ITEMS]
    const float* __restrict__ gmean,       // [1]
    float*       __restrict__ out)         // [BATCH] pred ++ [BATCH,128] feat
{
    const int warp_gid = (blockIdx.x * blockDim.x + threadIdx.x) >> 5;
    const int lane     = threadIdx.x & 31;
    const int half     = lane >> 4;       // which row of each pair
    const int sub      = lane & 15;       // lane within 16-lane subwarp

    const float gm = __ldg(gmean);

    // Persistent grid-stride over row-groups: no wave-quantization tail,
    // and successive iterations pipeline loads against draining stores.
    for (int g = warp_gid; g < NGROUPS; g += WARPS_TOTAL) {
        const int row0 = g * RPW + half;   // rows: row0 + 2*i, i=0..3

        // ---- batch index loads (1MB array, L2 resident) ----
        int2 ids[4];
        #pragma unroll
        for (int i = 0; i < 4; ++i)
            ids[i] = __ldg(((const int2*)user_item) + row0 + 2 * i);

        // ---- all 8 independent 16B embedding loads back-to-back (max MLP) ----
        float4 p[4], q[4];
        #pragma unroll
        for (int i = 0; i < 4; ++i) {
            p[i] = __ldg(((const float4*)(pu + (size_t)ids[i].x * NF)) + sub);
            q[i] = __ldg(((const float4*)(qi + (size_t)ids[i].y * NF)) + sub);
        }

        // ---- bias gathers overlap the row loads ----
        float bsum[4];
        #pragma unroll
        for (int i = 0; i < 4; ++i)
            if (sub == 0)
                bsum[i] = __ldg(bu + ids[i].x) + __ldg(bi + ids[i].y);

        // ---- per-row: dot, 16-lane reduce, streaming stores ----
        #pragma unroll
        for (int i = 0; i < 4; ++i) {
            const int row = row0 + 2 * i;

            float partial = p[i].x * q[i].x + p[i].y * q[i].y
                          + p[i].z * q[i].z + p[i].w * q[i].w;
            #pragma unroll
            for (int off = 8; off > 0; off >>= 1)
                partial += __shfl_xor_sync(0xffffffffu, partial, off, 16);

            // features: [p(64) | q(64)] = 32 float4 per row (write-once stream)
            float4* frow = (float4*)(out + (size_t)BATCH + (size_t)row * (2 * NF));
            __stcs(frow + sub,      p[i]);
            __stcs(frow + sub + 16, q[i]);

            if (sub == 0) {
                float v = gm + bsum[i] + partial;
                v = fminf(fmaxf(v, 1.0f), 5.0f);
                __stcs(out + row, v);
            }
        }
    }
}

extern "C" void kernel_launch(void* const* d_in, const int* in_sizes, int n_in,
                              void* d_out, int out_size)
{
    const int*   user_item = (const int*)  d_in[0];
    const float* pu        = (const float*)d_in[1];
    const float* qi        = (const float*)d_in[2];
    const float* bu        = (const float*)d_in[3];
    const float* bi        = (const float*)d_in[4];
    const float* gmean     = (const float*)d_in[5];
    float*       out       = (float*)d_out;

    svd_predict_kernel<<<GRID, 256>>>(user_item, pu, qi, bu, bi, gmean, out);
}

// round 9
// speedup vs baseline: 1.1830x; 1.1830x over previous
#include <cuda_runtime.h>
#include <cstdint>

#define BATCH 131072
#define NF    64
#define RPW   8   // rows per warp (4 pairs; 16-lane subwarp per row)

// 128-thread blocks, 12/SM: 48 warps/SM ceiling, fine-grained tail drain.
__global__ __launch_bounds__(128, 12) void svd_predict_kernel(
    const int*   __restrict__ user_item,   // [BATCH, 2]
    const float* __restrict__ pu,          // [N_USERS, 64]
    const float* __restrict__ qi,          // [N_ITEMS, 64]
    const float* __restrict__ bu,          // [N_USERS]
    const float* __restrict__ bi,          // [N_ITEMS]
    const float* __restrict__ gmean,       // [1]
    float*       __restrict__ out)         // [BATCH] pred ++ [BATCH,128] feat
{
    const int warp_id = (blockIdx.x * blockDim.x + threadIdx.x) >> 5;
    const int lane    = threadIdx.x & 31;
    const int half    = lane >> 4;        // which row of each pair
    const int sub     = lane & 15;        // lane within 16-lane subwarp
    const int base    = warp_id * RPW;    // group's first row
    const int row0    = base + half;      // this subwarp's rows: row0 + 2*i

    // ---- ids for embedding addressing (broadcast within subwarp) ----
    int2 ids[4];
    #pragma unroll
    for (int i = 0; i < 4; ++i)
        ids[i] = __ldg(((const int2*)user_item) + row0 + 2 * i);

    // ---- all 8 independent 16B embedding loads back-to-back (max MLP) ----
    float4 p[4], q[4];
    #pragma unroll
    for (int i = 0; i < 4; ++i) {
        p[i] = __ldg(((const float4*)(pu + (size_t)ids[i].x * NF)) + sub);
        q[i] = __ldg(((const float4*)(qi + (size_t)ids[i].y * NF)) + sub);
    }

    // ---- bias gathers as 2 full LDGs instead of 8 two-lane LDGs ----
    // lane c<16: r=c&7 -> own id pair; c<8 loads bu[uid_r], 8<=c<16 loads bi[iid_r]
    float bval = 0.0f;
    {
        const int r = lane & 7;
        const int2 idp = __ldg(((const int2*)user_item) + base + r);  // L1/L2 hit
        if (lane < 16)
            bval = (lane < 8) ? __ldg(bu + idp.x) : __ldg(bi + idp.y);
    }
    const float gm = __ldg(gmean);

    // ---- per-row: dot, 16-lane reduce, bias via shuffle, streaming stores ----
    #pragma unroll
    for (int i = 0; i < 4; ++i) {
        const int row = row0 + 2 * i;

        float partial = p[i].x * q[i].x + p[i].y * q[i].y
                      + p[i].z * q[i].z + p[i].w * q[i].w;
        #pragma unroll
        for (int off = 8; off > 0; off >>= 1)
            partial += __shfl_xor_sync(0xffffffffu, partial, off, 16);

        // bias sum for this subwarp's row: bu from lane (2i+half), bi from lane (8+2i+half)
        const float b_u = __shfl_sync(0xffffffffu, bval, 2 * i + half);
        const float b_i = __shfl_sync(0xffffffffu, bval, 8 + 2 * i + half);

        // features: [p(64) | q(64)] = 32 float4 per row (write-once stream)
        float4* frow = (float4*)(out + (size_t)BATCH + (size_t)row * (2 * NF));
        __stcs(frow + sub,      p[i]);
        __stcs(frow + sub + 16, q[i]);

        if (sub == 0) {
            float v = gm + b_u + b_i + partial;
            v = fminf(fmaxf(v, 1.0f), 5.0f);
            __stcs(out + row, v);
        }
    }
}

extern "C" void kernel_launch(void* const* d_in, const int* in_sizes, int n_in,
                              void* d_out, int out_size)
{
    const int*   user_item = (const int*)  d_in[0];
    const float* pu        = (const float*)d_in[1];
    const float* qi        = (const float*)d_in[2];
    const float* bu        = (const float*)d_in[3];
    const float* bi        = (const float*)d_in[4];
    const float* gmean     = (const float*)d_in[5];
    float*       out       = (float*)d_out;

    // 128 threads = 4 warps = 32 rows per block
    const int rows_per_block = (128 / 32) * RPW;                 // 32
    const int grid = (BATCH + rows_per_block - 1) / rows_per_block;  // 4096
    svd_predict_kernel<<<grid, 128>>>(user_item, pu, qi, bu, bi, gmean, out);
}

// round 12
// speedup vs baseline: 1.2756x; 1.0783x over previous
#include <cuda_runtime.h>
#include <cstdint>

#define BATCH 131072
#define NF    64
#define RPW   8   // rows per warp (4 pairs; 16-lane subwarp per row)

// 16B embedding load with L2 evict_last cache-hint policy: read working set
// (~59MB unique rows) fits in the 126MB L2, so across graph replays reads
// become L2 hits while the evict-first write stream passes through.
static __device__ __forceinline__ float4 ldg_evict_last(const float4* p, uint64_t pol) {
    float4 r;
    asm volatile("ld.global.nc.L2::cache_hint.v4.f32 {%0,%1,%2,%3}, [%4], %5;"
                 : "=f"(r.x), "=f"(r.y), "=f"(r.z), "=f"(r.w)
                 : "l"(p), "l"(pol));
    return r;
}

__global__ __launch_bounds__(256, 6) void svd_predict_kernel(
    const int*   __restrict__ user_item,   // [BATCH, 2]
    const float* __restrict__ pu,          // [N_USERS, 64]
    const float* __restrict__ qi,          // [N_ITEMS, 64]
    const float* __restrict__ bu,          // [N_USERS]
    const float* __restrict__ bi,          // [N_ITEMS]
    const float* __restrict__ gmean,       // [1]
    float*       __restrict__ out)         // [BATCH] pred ++ [BATCH,128] feat
{
    const int warp_id = (blockIdx.x * blockDim.x + threadIdx.x) >> 5;
    const int lane    = threadIdx.x & 31;
    const int half    = lane >> 4;        // which row of the pair
    const int sub     = lane & 15;        // lane within 16-lane subwarp
    const int row0    = warp_id * RPW + half;   // rows: row0 + 2*i, i=0..3

    // L2 evict_last policy descriptor (fraction = 1.0)
    uint64_t pol;
    asm("createpolicy.fractional.L2::evict_last.b64 %0, 1.0;" : "=l"(pol));

    // ---- batch all index loads (1MB array, L2 resident) ----
    int2 ids[4];
    #pragma unroll
    for (int i = 0; i < 4; ++i)
        ids[i] = __ldg(((const int2*)user_item) + row0 + 2 * i);

    // ---- all 8 independent 16B embedding loads back-to-back (max MLP),
    //      L2-pinned so replays hit in L2 ----
    float4 p[4], q[4];
    #pragma unroll
    for (int i = 0; i < 4; ++i) {
        p[i] = ldg_evict_last(((const float4*)(pu + (size_t)ids[i].x * NF)) + sub, pol);
        q[i] = ldg_evict_last(((const float4*)(qi + (size_t)ids[i].y * NF)) + sub, pol);
    }

    // ---- bias gathers (small tables, L2-resident) overlap the row loads ----
    float bsum[4];
    #pragma unroll
    for (int i = 0; i < 4; ++i)
        if (sub == 0)
            bsum[i] = __ldg(bu + ids[i].x) + __ldg(bi + ids[i].y);

    const float gm = __ldg(gmean);

    // ---- per-row: dot, 16-lane reduce, streaming stores ----
    #pragma unroll
    for (int i = 0; i < 4; ++i) {
        const int row = row0 + 2 * i;

        float partial = p[i].x * q[i].x + p[i].y * q[i].y
                      + p[i].z * q[i].z + p[i].w * q[i].w;
        #pragma unroll
        for (int off = 8; off > 0; off >>= 1)
            partial += __shfl_xor_sync(0xffffffffu, partial, off, 16);

        // features: [p(64) | q(64)] = 32 float4 per row (write-once stream,
        // evict-first so it doesn't displace the pinned read set)
        float4* frow = (float4*)(out + (size_t)BATCH + (size_t)row * (2 * NF));
        __stcs(frow + sub,      p[i]);
        __stcs(frow + sub + 16, q[i]);

        if (sub == 0) {
            float v = gm + bsum[i] + partial;
            v = fminf(fmaxf(v, 1.0f), 5.0f);
            __stcs(out + row, v);
        }
    }
}

extern "C" void kernel_launch(void* const* d_in, const int* in_sizes, int n_in,
                              void* d_out, int out_size)
{
    const int*   user_item = (const int*)  d_in[0];
    const float* pu        = (const float*)d_in[1];
    const float* qi        = (const float*)d_in[2];
    const float* bu        = (const float*)d_in[3];
    const float* bi        = (const float*)d_in[4];
    const float* gmean     = (const float*)d_in[5];
    float*       out       = (float*)d_out;

    const int rows_per_block = (256 / 32) * RPW;   // 64
    const int grid = (BATCH + rows_per_block - 1) / rows_per_block;  // 2048
    svd_predict_kernel<<<grid, 256>>>(user_item, pu, qi, bu, bi, gmean, out);
}